// round 14
// baseline (speedup 1.0000x reference)
#include <cuda_runtime.h>
#include <cuda_bf16.h>
#include <math.h>

// ---------------------------------------------------------------------------
// Geo_HR_SNN — fp32 bit-matching implementation (XLA:GPU-shaped numerics).
// NUMERICS CONTRACT (validated R6, rel_err 5.8136e-07 — do not change):
//   * conv / dense / fc: ascending-k single-accumulator fp32 FMA chains
//   * BN: non-contracted ((x-m)*rsqrtf(v+eps))*s + b, rsqrtf = __nv_rsqrtf
//   * sigmoid: 0.5 + 0.5*tanh(0.5x) with XLA f32 rational tanh
//   * scan: strictly non-contracted mul/add
// R13 perf changes (order-preserving): attack the STALL bound with occupancy.
//   * TT=16, 128 threads, launch_bounds(128,4): 4 CTAs/SM (smem 47KB,
//     regs ~110) — 4-way inter-CTA overlap of staging/phase1/phase2.
//   * phase 2 uses ALL threads (16t x 8hq, 1t x 4h each) — R11 idled half
//     the block through its longest phase.
//   * cs stride 17 (odd): conflict-free stores (cc pattern) AND reads.
//   * fc: 256 threads (batch-pair per thread) for 2x latency hiding.
// ---------------------------------------------------------------------------

#define B_      1024
#define T_      320
#define EEG_CH  64
#define GEO_CH  18
#define HID     32
#define KW      32
#define TT      16          // t-tile

typedef unsigned long long ull;

// packed helpers: each half is an independent IEEE .rn fp32 op (bit-exact)
#define FMA2(d, a, b, c) \
    asm("fma.rn.f32x2 %0, %1, %2, %3;" : "=l"(d) : "l"(a), "l"(b), "l"(c))
#define PACK2(out, lo, hi) \
    asm("mov.b64 %0, {%1, %2};" : "=l"(out) : "f"(lo), "f"(hi))
#define UNPACK2(lo, hi, in) \
    asm("mov.b64 {%0, %1}, %2;" : "=f"(lo), "=f"(hi) : "l"(in))

// scratch (static device globals: allocation-free)
__device__ float g_enc_eeg[(size_t)B_ * T_ * HID];
__device__ float g_enc_geo[(size_t)B_ * T_ * HID];
__device__ float g_dp[(size_t)B_ * 320];

// ---------------------------------------------------------------------------
// XLA f32 tanh rational approximation, non-contracted.
// ---------------------------------------------------------------------------
__device__ __forceinline__ float tanh_xla(float x) {
    const float kMax = 7.90531110763549805f;
    float xc = fminf(fmaxf(x, -kMax), kMax);
    float x2 = __fmul_rn(xc, xc);
    float p = -2.76076847742355e-16f;
    p = __fadd_rn(__fmul_rn(p, x2), 2.00018790482477e-13f);
    p = __fadd_rn(__fmul_rn(p, x2), -8.60467152213735e-11f);
    p = __fadd_rn(__fmul_rn(p, x2), 5.12229709037114e-08f);
    p = __fadd_rn(__fmul_rn(p, x2), 1.48572235717979e-05f);
    p = __fadd_rn(__fmul_rn(p, x2), 6.37261928875436e-04f);
    p = __fadd_rn(__fmul_rn(p, x2), 4.89352455891786e-03f);
    float num = __fmul_rn(xc, p);
    float q = 1.19825839466702e-06f;
    q = __fadd_rn(__fmul_rn(q, x2), 1.18534705686654e-04f);
    q = __fadd_rn(__fmul_rn(q, x2), 2.26843463243900e-03f);
    q = __fadd_rn(__fmul_rn(q, x2), 4.89352518554385e-03f);
    float r = __fdiv_rn(num, q);
    return (fabsf(x) < 0.0004f) ? x : r;
}

__device__ __forceinline__ float sigmoid_xla(float x) {
    return __fadd_rn(0.5f, __fmul_rn(0.5f, tanh_xla(__fmul_rn(0.5f, x))));
}

// ---------------------------------------------------------------------------
// Fused encoder. Block = (one batch b) x (16-wide t tile). 128 threads,
// 4 CTAs/SM. Phase 1: conv+BN1 -> cs, channel pairs (cc,cc+4) FFMA2-packed,
// x-stationary 8-wide t-groups, pairs strided by 128 threads.
// Phase 2: dense+BN2+act, ALL 128 threads (tl 0..15, hq 0..7), weights __ldg.
// ---------------------------------------------------------------------------
template <int IC, bool IS_RELU>
__global__ __launch_bounds__(128, 4)
void enc_kernel(const float* __restrict__ x,
                const float* __restrict__ convw, const float* __restrict__ convb,
                const float* __restrict__ b1s, const float* __restrict__ b1b,
                const float* __restrict__ b1m, const float* __restrict__ b1v,
                const float* __restrict__ dw, const float* __restrict__ db,
                const float* __restrict__ b2s, const float* __restrict__ b2b,
                const float* __restrict__ b2m, const float* __restrict__ b2v,
                float* __restrict__ out)
{
    constexpr int CC = IC * 8;
    constexpr int NPAIR = CC / 2;               // channel pairs (cc, cc+4)
    constexpr int XR = TT + 31;                 // 47 staged rows
    constexpr int XS_ELE = XR * IC;
    constexpr int XS_PAD = (XS_ELE + 3) & ~3;
    constexpr int CSTRIDE = TT + 1;             // 17 (odd): conflict-free
    extern __shared__ __align__(16) float smem[];
    float* xs = smem;                 // [47][IC]   conv input
    float* cs = smem + XS_PAD;        // [CC][17]   BN1 output

    const int b  = blockIdx.y;
    const int t0 = blockIdx.x * TT;
    const int tid = threadIdx.x;

    // stage x rows [t0-15, t0+TT+15] (47 rows), zeros outside [0,T)
    const long base_in = (long)b * T_ * IC + (long)(t0 - 15) * IC;
    for (int i = tid; i < XS_ELE; i += 128) {
        int j = i / IC;
        int t = t0 - 15 + j;
        float v = 0.f;
        if (t >= 0 && t < T_) v = x[base_in + i];
        xs[i] = v;
    }
    __syncthreads();

    // ---- Phase 1: depthwise conv + bias + BN1 (FFMA2, 8-wide t-groups) ----
#pragma unroll 1
    for (int pr = tid; pr < NPAIR; pr += 128) {
        const int cc  = (pr >> 2) * 8 + (pr & 3);   // lo channel
        const int cc2 = cc + 4;                     // hi channel (same ic)
        const int ic  = pr >> 2;
        ull wp[KW];
#pragma unroll
        for (int k = 0; k < KW; ++k)
            PACK2(wp[k], convw[k * CC + cc], convw[k * CC + cc2]);
        const float cbl = convb[cc],  cbh = convb[cc2];
        const float ml  = b1m[cc],    mh  = b1m[cc2];
        const float scl = b1s[cc],    sch = b1s[cc2];
        const float bbl = b1b[cc],    bbh = b1b[cc2];
        const float rl  = rsqrtf(__fadd_rn(b1v[cc],  1e-5f));
        const float rh  = rsqrtf(__fadd_rn(b1v[cc2], 1e-5f));
#pragma unroll 1
        for (int g = 0; g < TT / 8; ++g) {
            const int tg = g * 8;
            ull a[8];
#pragma unroll
            for (int j = 0; j < 8; ++j) a[j] = 0ull;   // (+0,+0)
            // out[j] = sum_k x[tg+j+k]*w[k]; s = j+k ascending keeps
            // ascending-k order for EVERY j and BOTH components.
#pragma unroll
            for (int s = 0; s < 39; ++s) {
                const float xv = xs[(tg + s) * IC + ic];
                ull xp; PACK2(xp, xv, xv);
#pragma unroll
                for (int j = 0; j < 8; ++j)
                    if (s >= j && s <= j + 31)
                        FMA2(a[j], xp, wp[s - j], a[j]);
            }
#pragma unroll
            for (int j = 0; j < 8; ++j) {
                float al, ah; UNPACK2(al, ah, a[j]);
                float cl = __fadd_rn(al, cbl);
                cl = __fmul_rn(__fsub_rn(cl, ml), rl);
                cl = __fadd_rn(__fmul_rn(cl, scl), bbl);
                cs[cc * CSTRIDE + tg + j] = cl;
                float ch = __fadd_rn(ah, cbh);
                ch = __fmul_rn(__fsub_rn(ch, mh), rh);
                ch = __fadd_rn(__fmul_rn(ch, sch), bbh);
                cs[cc2 * CSTRIDE + tg + j] = ch;
            }
        }
    }
    __syncthreads();

    // ---- Phase 2: dense + bias + BN2 + activation (all 128 threads) ----
    {
        const int tl = tid >> 3;   // 0..15
        const int hq = tid & 7;    // 0..7
        ull acc01 = 0ull, acc23 = 0ull;   // (h0,h1), (h2,h3)
        const float4* dwv = reinterpret_cast<const float4*>(dw);
#pragma unroll 4
        for (int cc = 0; cc < CC; ++cc) {
            const float c = cs[cc * CSTRIDE + tl];
            ull cp; PACK2(cp, c, c);
            union { float4 f; ull u[2]; } w;
            w.f = __ldg(dwv + cc * 8 + hq);
            FMA2(acc01, cp, w.u[0], acc01);
            FMA2(acc23, cp, w.u[1], acc23);
        }
        float av[4];
        UNPACK2(av[0], av[1], acc01);
        UNPACK2(av[2], av[3], acc23);

        const float4 dbq = reinterpret_cast<const float4*>(db)[hq];
        const float4 mq  = reinterpret_cast<const float4*>(b2m)[hq];
        const float4 vq  = reinterpret_cast<const float4*>(b2v)[hq];
        const float4 sq  = reinterpret_cast<const float4*>(b2s)[hq];
        const float4 bq  = reinterpret_cast<const float4*>(b2b)[hq];
        float dbv[4] = {dbq.x, dbq.y, dbq.z, dbq.w};
        float mv[4]  = {mq.x, mq.y, mq.z, mq.w};
        float vv[4]  = {vq.x, vq.y, vq.z, vq.w};
        float sv[4]  = {sq.x, sq.y, sq.z, sq.w};
        float bv[4]  = {bq.x, bq.y, bq.z, bq.w};

        float o[4];
#pragma unroll
        for (int j = 0; j < 4; ++j) {
            float d = __fadd_rn(av[j], dbv[j]);
            float r2 = rsqrtf(__fadd_rn(vv[j], 1e-5f));          // __nv_rsqrtf
            d = __fmul_rn(__fsub_rn(d, mv[j]), r2);
            d = __fadd_rn(__fmul_rn(d, sv[j]), bv[j]);
            o[j] = IS_RELU ? fmaxf(d, 0.f) : sigmoid_xla(d);
        }
        reinterpret_cast<float4*>(
            out + ((long)b * T_ + t0 + tl) * HID)[hq] =
            make_float4(o[0], o[1], o[2], o[3]);
    }
}

// ---------------------------------------------------------------------------
// SNN scan: one thread per (b,h) lane; strictly non-contracted arithmetic.
// ---------------------------------------------------------------------------
__global__ __launch_bounds__(256)
void scan_kernel(const float* __restrict__ enc_e, const float* __restrict__ enc_g,
                 const float* __restrict__ gamma, float* __restrict__ dp)
{
    int gid = blockIdx.x * blockDim.x + threadIdx.x;   // 0..32767
    int b = gid >> 5;
    int h = gid & 31;
    float g = gamma[h];

    const float* pe = enc_e + (long)b * T_ * HID + h;
    const float* pg = enc_g + (long)b * T_ * HID + h;

    float m1 = 0.f, m2 = 0.f, m3 = 0.f, ma = 0.f, eta = 0.f, mli = 0.f, prev = 0.f;
    float neg = 0.f, pos = 0.f;
    int w = 0;

#pragma unroll 4
    for (int t = 0; t < T_; ++t) {
        float ce = pe[t * HID];
        float cg = pg[t * HID];

        m1 = __fadd_rn(__fmul_rn(0.9f, m1), ce);
        float s1 = (__fsub_rn(m1, 0.7f) >= 0.f) ? 1.f : 0.f;
        m1 = __fmul_rn(m1, __fsub_rn(1.f, s1));
        m2 = __fadd_rn(__fmul_rn(0.8f, m2), ce);
        float s2 = (__fsub_rn(m2, 0.5f) >= 0.f) ? 1.f : 0.f;
        m2 = __fmul_rn(m2, __fsub_rn(1.f, s2));
        m3 = __fadd_rn(__fmul_rn(0.6f, m3), ce);
        float s3 = (__fsub_rn(m3, 0.3f) >= 0.f) ? 1.f : 0.f;
        m3 = __fmul_rn(m3, __fsub_rn(1.f, s3));
        float hr = __fdiv_rn(__fadd_rn(__fadd_rn(s1, s2), s3), 3.0f);

        eta = __fadd_rn(__fmul_rn(0.36f, eta), __fmul_rn(0.64f, prev));
        float theta = __fsub_rn(__fadd_rn(0.5f, __fmul_rn(1.8f, eta)),
                                __fmul_rn(g, cg));
        ma = __fadd_rn(__fmul_rn(0.8f, ma), hr);
        float sa = (__fsub_rn(ma, theta) >= 0.f) ? 1.f : 0.f;
        ma = __fmul_rn(ma, __fsub_rn(1.f, sa));
        mli = __fadd_rn(__fmul_rn(0.9f, mli), sa);
        prev = sa;

        int p = t & 31;
        if (p < 16) neg = __fadd_rn(neg, mli); else pos = __fadd_rn(pos, mli);
        if (p == 31) {
            dp[(long)b * 320 + h * 10 + w] =
                __fsub_rn(__fdiv_rn(pos, 16.f), __fdiv_rn(neg, 16.f));
            pos = 0.f; neg = 0.f; ++w;
        }
    }
}

// ---------------------------------------------------------------------------
// FC head: out = elu(dp @ fc1 + b1) @ fc2 + b2.  4 batch rows per block,
// 256 threads: thread = (h = tid&127, batch-pair = tid>>7) — each chain is
// the unchanged ascending-i / ascending-j order.
// ---------------------------------------------------------------------------
#define FC_BATCH 4
__global__ __launch_bounds__(256)
void fc_kernel(const float* __restrict__ dp,
               const float* __restrict__ w1, const float* __restrict__ b1,
               const float* __restrict__ w2, const float* __restrict__ b2,
               float* __restrict__ out)
{
    __shared__ float xr[FC_BATCH][320];
    __shared__ float h1[FC_BATCH][129];
    const int b0 = blockIdx.x * FC_BATCH;
    const int tid = threadIdx.x;
    const int hh = tid & 127;
    const int qh = tid >> 7;        // 0/1 -> batches {0,1} or {2,3}

    for (int i = tid; i < FC_BATCH * 320; i += 256)
        xr[i / 320][i % 320] = dp[(long)(b0 + i / 320) * 320 + (i % 320)];
    __syncthreads();

    float a[2] = {0.f, 0.f};
#pragma unroll 4
    for (int i = 0; i < 320; ++i) {
        const float w = w1[i * 128 + hh];
        a[0] = fmaf(xr[qh * 2 + 0][i], w, a[0]);
        a[1] = fmaf(xr[qh * 2 + 1][i], w, a[1]);
    }
    const float bb = b1[hh];
#pragma unroll
    for (int q = 0; q < 2; ++q) {
        float aa = __fadd_rn(a[q], bb);
        h1[qh * 2 + q][hh] = (aa > 0.f) ? aa : expm1f(aa);
    }
    __syncthreads();

    if (tid < FC_BATCH * 4) {
        const int q = tid >> 2;
        const int oo = tid & 3;
        float o = 0.f;
#pragma unroll 4
        for (int j = 0; j < 128; ++j) o = fmaf(h1[q][j], w2[j * 4 + oo], o);
        out[(long)(b0 + q) * 4 + oo] = __fadd_rn(o, b2[oo]);
    }
}

// ---------------------------------------------------------------------------
extern "C" void kernel_launch(void* const* d_in, const int* in_sizes, int n_in,
                              void* d_out, int out_size)
{
    const float* x_eeg = (const float*)d_in[0];
    const float* x_geo = (const float*)d_in[1];
    const float* ec_w = (const float*)d_in[2];
    const float* ec_b = (const float*)d_in[3];
    const float* e1s = (const float*)d_in[4];
    const float* e1b = (const float*)d_in[5];
    const float* e1m = (const float*)d_in[6];
    const float* e1v = (const float*)d_in[7];
    const float* ed_w = (const float*)d_in[8];
    const float* ed_b = (const float*)d_in[9];
    const float* e2s = (const float*)d_in[10];
    const float* e2b = (const float*)d_in[11];
    const float* e2m = (const float*)d_in[12];
    const float* e2v = (const float*)d_in[13];
    const float* gc_w = (const float*)d_in[14];
    const float* gc_b = (const float*)d_in[15];
    const float* g1s = (const float*)d_in[16];
    const float* g1b = (const float*)d_in[17];
    const float* g1m = (const float*)d_in[18];
    const float* g1v = (const float*)d_in[19];
    const float* gd_w = (const float*)d_in[20];
    const float* gd_b = (const float*)d_in[21];
    const float* g2s = (const float*)d_in[22];
    const float* g2b = (const float*)d_in[23];
    const float* g2m = (const float*)d_in[24];
    const float* g2v = (const float*)d_in[25];
    const float* gamma = (const float*)d_in[26];
    const float* fc1_w = (const float*)d_in[27];
    const float* fc1_b = (const float*)d_in[28];
    const float* fc2_w = (const float*)d_in[29];
    const float* fc2_b = (const float*)d_in[30];
    float* out = (float*)d_out;

    float *p_enc_e, *p_enc_g, *p_dp;
    cudaGetSymbolAddress((void**)&p_enc_e, g_enc_eeg);
    cudaGetSymbolAddress((void**)&p_enc_g, g_enc_geo);
    cudaGetSymbolAddress((void**)&p_dp, g_dp);

    const int CCE = EEG_CH * 8, CCG = GEO_CH * 8;
    const int smem_e = ((((TT + 31) * EEG_CH + 3) & ~3) + CCE * (TT + 1)) * 4;
    const int smem_g = ((((TT + 31) * GEO_CH + 3) & ~3) + CCG * (TT + 1)) * 4;
    cudaFuncSetAttribute((const void*)enc_kernel<EEG_CH, true>,
                         cudaFuncAttributeMaxDynamicSharedMemorySize, smem_e);
    cudaFuncSetAttribute((const void*)enc_kernel<GEO_CH, false>,
                         cudaFuncAttributeMaxDynamicSharedMemorySize, smem_g);

    dim3 ge(T_ / TT, B_);
    enc_kernel<EEG_CH, true><<<ge, 128, smem_e>>>(
        x_eeg, ec_w, ec_b, e1s, e1b, e1m, e1v,
        ed_w, ed_b, e2s, e2b, e2m, e2v, p_enc_e);
    enc_kernel<GEO_CH, false><<<ge, 128, smem_g>>>(
        x_geo, gc_w, gc_b, g1s, g1b, g1m, g1v,
        gd_w, gd_b, g2s, g2b, g2m, g2v, p_enc_g);

    scan_kernel<<<(B_ * HID) / 256, 256>>>(p_enc_e, p_enc_g, gamma, p_dp);

    fc_kernel<<<B_ / FC_BATCH, 256>>>(p_dp, fc1_w, fc1_b, fc2_w, fc2_b, out);
}